// round 5
// baseline (speedup 1.0000x reference)
#include <cuda_runtime.h>

#define C    256
#define CH   128
#define HWn  262144
#define HW4  65536
#define TOT4 16777216          // C*HW4
#define SEGS 16
#define SEG_F4 4096
#define EPS  1e-5f
#define CSPL 8                 // channel groups in k3a (32 channels each)

__device__ float d_partials[C * SEGS];
__device__ float d_g[C];
__device__ float d_v[C];
__device__ float d_b0;
__device__ float d_ybp[CSPL * HWn];   // 8 MB partial yb planes
__device__ float d_sy[HWn];           // 1 MB sigmoid(yb) plane

// ---------------- Kernel 1: per-channel spatial sums -----------------------------
__global__ void k1_sums(const float4* __restrict__ x4) {
    const int c = blockIdx.y, seg = blockIdx.x, t = threadIdx.x;
    const float4* xc = x4 + (size_t)c * HW4 + (size_t)seg * SEG_F4;
    float s = 0.f;
#pragma unroll
    for (int j = 0; j < 16; j++) {
        float4 u = xc[t + j * 256];
        s += (u.x + u.y) + (u.z + u.w);
    }
    __shared__ float red[256];
    red[t] = s;
    __syncthreads();
    for (int off = 128; off > 0; off >>= 1) {
        if (t < off) red[t] += red[t + off];
        __syncthreads();
    }
    if (t == 0) d_partials[c * SEGS + seg] = red[0];
}

// ---------------- Kernel 2: tiny algebra (1 block) -------------------------------
__global__ void k2_scalars(const float* __restrict__ cv1w, const float* __restrict__ cv1b,
                           const float* __restrict__ cv3w, const float* __restrict__ cv3b,
                           const float* __restrict__ lng,  const float* __restrict__ lnb,
                           const float* __restrict__ sp1w, const float* __restrict__ sp1b,
                           const float* __restrict__ sp2w, const float* __restrict__ sp2b) {
    __shared__ float S[C];
    __shared__ float ybuf[CH];
    __shared__ float s2[CH];
    __shared__ float wsm[CH];
    __shared__ float red[256];
    const int t = threadIdx.x;

    {
        float s = 0.f;
#pragma unroll
        for (int j = 0; j < SEGS; j++) s += d_partials[t * SEGS + j];
        S[t] = s;
    }
    __syncthreads();

    if (t < CH) {
        float a = 0.f;
        for (int c = 0; c < C; c++) a += cv1w[t * C + c] * S[c];
        ybuf[t] = a + (float)HWn * cv1b[t];
    } else {
        const int u = t - CH;
        float a = 0.f;
        for (int c = 0; c < C; c++) a += sp2w[u * C + c] * S[c];
        s2[u] = a * (1.f / (float)HWn) + sp2b[u];
    }
    __syncthreads();

    float zv = cv3b[t];
    for (int c = 0; c < CH; c++) zv += cv3w[t * CH + c] * ybuf[c];

    red[t] = zv;
    __syncthreads();
    for (int off = 128; off > 0; off >>= 1) {
        if (t < off) red[t] += red[t + off];
        __syncthreads();
    }
    const float mu = red[0] * (1.f / (float)C);
    __syncthreads();
    red[t] = zv * zv;
    __syncthreads();
    for (int off = 128; off > 0; off >>= 1) {
        if (t < off) red[t] += red[t + off];
        __syncthreads();
    }
    const float var = red[0] * (1.f / (float)C) - mu * mu;
    __syncthreads();

    const float zn = (zv - mu) * rsqrtf(var + EPS) * lng[t] + lnb[t];
    d_g[t] = 1.f / (1.f + expf(-zn));

    red[t] = (t < CH) ? s2[t] : -1e30f;
    __syncthreads();
    for (int off = 128; off > 0; off >>= 1) {
        if (t < off) red[t] = fmaxf(red[t], red[t + off]);
        __syncthreads();
    }
    const float mx = red[0];
    __syncthreads();
    red[t] = (t < CH) ? expf(s2[t] - mx) : 0.f;
    __syncthreads();
    for (int off = 128; off > 0; off >>= 1) {
        if (t < off) red[t] += red[t + off];
        __syncthreads();
    }
    const float denom = red[0];
    __syncthreads();
    if (t < CH) wsm[t] = expf(s2[t] - mx) / denom;
    __syncthreads();

    {
        float vv = 0.f;
        for (int c_ = 0; c_ < CH; c_++) vv += wsm[c_] * sp1w[c_ * C + t];
        d_v[t] = vv;
    }
    if (t == 0) {
        float b0 = 0.f;
        for (int c_ = 0; c_ < CH; c_++) b0 += wsm[c_] * sp1b[c_];
        d_b0 = b0;
    }
}

// ---------------- Kernel 3a: yb partial planes (contiguous reads, reg accum) ------
// grid (128, CSPL); block handles 2048 pixels (512 float4), sums 32 channels.
__global__ __launch_bounds__(256)
void k3a_yb(const float4* __restrict__ x4) {
    const int t = threadIdx.x;
    const int p4base = blockIdx.x * 512;
    const int c0 = blockIdx.y * 32;

    float4 a0 = {0.f, 0.f, 0.f, 0.f};
    float4 a1 = {0.f, 0.f, 0.f, 0.f};
#pragma unroll 4
    for (int j = 0; j < 32; j++) {
        const int c = c0 + j;
        const float vc = d_v[c];
        const float4* xp = x4 + (size_t)c * HW4 + p4base;
        float4 u0 = xp[t];
        float4 u1 = xp[t + 256];
        a0.x += vc * u0.x; a0.y += vc * u0.y; a0.z += vc * u0.z; a0.w += vc * u0.w;
        a1.x += vc * u1.x; a1.y += vc * u1.y; a1.z += vc * u1.z; a1.w += vc * u1.w;
    }
    float4* yp = (float4*)(d_ybp + (size_t)blockIdx.y * HWn) + p4base;
    yp[t] = a0;
    yp[t + 256] = a1;
}

// ---------------- Kernel 3s: combine partials + sigmoid -> sy plane ---------------
__global__ __launch_bounds__(256)
void k3sy() {
    const float b0 = d_b0;
    const int i4 = blockIdx.x * 256 + threadIdx.x;   // grid = 65536/256 blocks? -> 256 blocks
    {
        float4 s = {b0, b0, b0, b0};
#pragma unroll
        for (int g = 0; g < CSPL; g++) {
            float4 u = ((const float4*)(d_ybp + (size_t)g * HWn))[i4];
            s.x += u.x; s.y += u.y; s.z += u.z; s.w += u.w;
        }
        float4 o;
        o.x = 1.f / (1.f + expf(-s.x));
        o.y = 1.f / (1.f + expf(-s.y));
        o.z = 1.f / (1.f + expf(-s.z));
        o.w = 1.f / (1.f + expf(-s.w));
        ((float4*)d_sy)[i4] = o;
    }
}

// ---------------- Kernel 3b: pure streaming elementwise ---------------------------
// out[i] = (g[c] + sy[p]) * x[i], linear over the whole tensor.
__global__ __launch_bounds__(256)
void k3b_out(const float4* __restrict__ x4, float4* __restrict__ out4) {
    __shared__ float sg[C];
    sg[threadIdx.x] = d_g[threadIdx.x];
    __syncthreads();

    const int stride = gridDim.x * 256;
    const float4* __restrict__ sy4 = (const float4*)d_sy;
#pragma unroll 4
    for (int i4 = blockIdx.x * 256 + threadIdx.x; i4 < TOT4; i4 += stride) {
        const int c  = i4 >> 16;       // i4 / HW4
        const int p4 = i4 & 65535;     // i4 % HW4
        float4 xv = __ldcs(&x4[i4]);
        float4 s  = __ldg(&sy4[p4]);
        const float gv = sg[c];
        float4 o;
        o.x = (gv + s.x) * xv.x;
        o.y = (gv + s.y) * xv.y;
        o.z = (gv + s.z) * xv.z;
        o.w = (gv + s.w) * xv.w;
        __stcs(&out4[i4], o);
    }
}

// ---------------- Launch ----------------------------------------------------------
extern "C" void kernel_launch(void* const* d_in, const int* in_sizes, int n_in,
                              void* d_out, int out_size) {
    const float* x    = (const float*)d_in[0];
    const float* cv1w = (const float*)d_in[1];
    const float* cv1b = (const float*)d_in[2];
    // d_in[3], d_in[4] = ch_cv2_w/b : mathematically unused (softmax over size-1 dim)
    const float* cv3w = (const float*)d_in[5];
    const float* cv3b = (const float*)d_in[6];
    const float* lng  = (const float*)d_in[7];
    const float* lnb  = (const float*)d_in[8];
    const float* sp1w = (const float*)d_in[9];
    const float* sp1b = (const float*)d_in[10];
    const float* sp2w = (const float*)d_in[11];
    const float* sp2b = (const float*)d_in[12];

    int nsm = 148;
    cudaDeviceGetAttribute(&nsm, cudaDevAttrMultiProcessorCount, 0);

    dim3 g1(SEGS, C);
    k1_sums<<<g1, 256>>>((const float4*)x);
    k2_scalars<<<1, 256>>>(cv1w, cv1b, cv3w, cv3b, lng, lnb, sp1w, sp1b, sp2w, sp2b);

    dim3 g3a(128, CSPL);
    k3a_yb<<<g3a, 256>>>((const float4*)x);
    k3sy<<<HW4 / 256, 256>>>();
    k3b_out<<<nsm * 8, 256>>>((const float4*)x, (float4*)d_out);
}

// round 8
// speedup vs baseline: 1.1747x; 1.1747x over previous
#include <cuda_runtime.h>

#define C    256
#define CH   128
#define HWn  262144
#define HW4  65536
#define SEGS 16
#define SEG_F4 4096   // HW4 / SEGS
#define EPS  1e-5f

// k3 tiling: 32 pixels per tile, double-buffered; upper channels cp.async,
// lower channels register-staged __ldcs (evict-first)
#define TP     32
#define TP4    8
#define TILE_F  (C * TP)       // 8192 floats = 32 KB
#define NTILES  (HWn / TP)     // 8192 tiles

__device__ float d_partials[C * SEGS];
__device__ float d_g[C];
__device__ float d_v[C];
__device__ float d_b0;

// ---------------- Kernel 1: per-channel spatial sums ------------------------------
// Lower 128 channels: evict-first reads. Upper 128: normal -> stay L2-resident.
__global__ void k1_sums(const float4* __restrict__ x4) {
    const int c = blockIdx.y, seg = blockIdx.x, t = threadIdx.x;
    const float4* xc = x4 + (size_t)c * HW4 + (size_t)seg * SEG_F4;
    float s = 0.f;
    if (c < CH) {
#pragma unroll
        for (int j = 0; j < 16; j++) {
            float4 u = __ldcs(&xc[t + j * 256]);
            s += (u.x + u.y) + (u.z + u.w);
        }
    } else {
#pragma unroll
        for (int j = 0; j < 16; j++) {
            float4 u = xc[t + j * 256];
            s += (u.x + u.y) + (u.z + u.w);
        }
    }
    __shared__ float red[256];
    red[t] = s;
    __syncthreads();
    for (int off = 128; off > 0; off >>= 1) {
        if (t < off) red[t] += red[t + off];
        __syncthreads();
    }
    if (t == 0) d_partials[c * SEGS + seg] = red[0];
}

// ---------------- Kernel 2: all the tiny algebra (1 block) ------------------------
__global__ void k2_scalars(const float* __restrict__ cv1w, const float* __restrict__ cv1b,
                           const float* __restrict__ cv3w, const float* __restrict__ cv3b,
                           const float* __restrict__ lng,  const float* __restrict__ lnb,
                           const float* __restrict__ sp1w, const float* __restrict__ sp1b,
                           const float* __restrict__ sp2w, const float* __restrict__ sp2b) {
    __shared__ float S[C];
    __shared__ float ybuf[CH];
    __shared__ float s2[CH];
    __shared__ float wsm[CH];
    __shared__ float red[256];
    const int t = threadIdx.x;

    {
        float s = 0.f;
#pragma unroll
        for (int j = 0; j < SEGS; j++) s += d_partials[t * SEGS + j];
        S[t] = s;
    }
    __syncthreads();

    if (t < CH) {
        float a = 0.f;
        for (int c = 0; c < C; c++) a += cv1w[t * C + c] * S[c];
        ybuf[t] = a + (float)HWn * cv1b[t];
    } else {
        const int u = t - CH;
        float a = 0.f;
        for (int c = 0; c < C; c++) a += sp2w[u * C + c] * S[c];
        s2[u] = a * (1.f / (float)HWn) + sp2b[u];
    }
    __syncthreads();

    float zv = cv3b[t];
    for (int c = 0; c < CH; c++) zv += cv3w[t * CH + c] * ybuf[c];

    red[t] = zv;
    __syncthreads();
    for (int off = 128; off > 0; off >>= 1) {
        if (t < off) red[t] += red[t + off];
        __syncthreads();
    }
    const float mu = red[0] * (1.f / (float)C);
    __syncthreads();
    red[t] = zv * zv;
    __syncthreads();
    for (int off = 128; off > 0; off >>= 1) {
        if (t < off) red[t] += red[t + off];
        __syncthreads();
    }
    const float var = red[0] * (1.f / (float)C) - mu * mu;
    __syncthreads();

    const float zn = (zv - mu) * rsqrtf(var + EPS) * lng[t] + lnb[t];
    d_g[t] = 1.f / (1.f + expf(-zn));

    red[t] = (t < CH) ? s2[t] : -1e30f;
    __syncthreads();
    for (int off = 128; off > 0; off >>= 1) {
        if (t < off) red[t] = fmaxf(red[t], red[t + off]);
        __syncthreads();
    }
    const float mx = red[0];
    __syncthreads();
    red[t] = (t < CH) ? expf(s2[t] - mx) : 0.f;
    __syncthreads();
    for (int off = 128; off > 0; off >>= 1) {
        if (t < off) red[t] += red[t + off];
        __syncthreads();
    }
    const float denom = red[0];
    __syncthreads();
    if (t < CH) wsm[t] = expf(s2[t] - mx) / denom;
    __syncthreads();

    {
        float vv = 0.f;
        for (int c_ = 0; c_ < CH; c_++) vv += wsm[c_] * sp1w[c_ * C + t];
        d_v[t] = vv;
    }
    if (t == 0) {
        float b0 = 0.f;
        for (int c_ = 0; c_ < CH; c_++) b0 += wsm[c_] * sp1b[c_];
        d_b0 = b0;
    }
}

// ---------------- Kernel 3: hybrid pipelined fused yb + output --------------------
// Upper 128 channels via cp.async (normal policy -> L2 hits from k1 residency).
// Lower 128 channels via __ldcs into registers one tile ahead (evict-first).
__device__ __forceinline__ void k3_prefetch_upper(const float4* __restrict__ x4,
                                                  float* buf, int tile, int t) {
    unsigned dst_base = (unsigned)__cvta_generic_to_shared(buf);
    const int base4 = tile * TP4;
#pragma unroll
    for (int j = 4; j < 8; j++) {
        int i4 = t + j * 256;
        int c = i4 >> 3, p4 = i4 & 7;
        const float4* src = x4 + (size_t)c * HW4 + base4 + p4;
        unsigned dst = dst_base + i4 * 16;
        asm volatile("cp.async.cg.shared.global [%0], [%1], 16;\n" :: "r"(dst), "l"(src));
    }
    asm volatile("cp.async.commit_group;\n");
}

__device__ __forceinline__ void k3_load_lower(const float4* __restrict__ x4,
                                              float4* lr, int tile, int t) {
    const int base4 = tile * TP4;
#pragma unroll
    for (int j = 0; j < 4; j++) {
        int i4 = t + j * 256;
        int c = i4 >> 3, p4 = i4 & 7;
        lr[j] = __ldcs(&x4[(size_t)c * HW4 + base4 + p4]);
    }
}

__global__ __launch_bounds__(256, 3)
void k3_out(const float4* __restrict__ x4, float4* __restrict__ out4,
            int grid_stride) {
    extern __shared__ float sm[];
    float* buf0 = sm;                    // TILE_F
    float* buf1 = sm + TILE_F;           // TILE_F
    float* sv   = sm + 2 * TILE_F;       // C
    float* sg   = sv + C;                // C
    float* part = sg + C;                // 256
    float* sy   = part + 256;            // TP

    const int t = threadIdx.x;
    sv[t] = d_v[t];
    sg[t] = d_g[t];
    const float b0 = d_b0;

    int tile = blockIdx.x;
    if (tile >= NTILES) return;

    float4 lr[4];
    k3_load_lower(x4, lr, tile, t);
    k3_prefetch_upper(x4, buf0, tile, t);

    int i = 0;
    while (tile < NTILES) {
        float* cur = (i & 1) ? buf1 : buf0;
        float* nxt = (i & 1) ? buf0 : buf1;
        float4* cur4 = (float4*)cur;

        // stage current tile's lower half (loaded one iteration ago) into smem
#pragma unroll
        for (int j = 0; j < 4; j++) cur4[t + j * 256] = lr[j];

        const int ntile = tile + grid_stride;
        if (ntile < NTILES) {
            k3_load_lower(x4, lr, ntile, t);        // evict-first, covered by tile latency
            k3_prefetch_upper(x4, nxt, ntile, t);
            asm volatile("cp.async.wait_group 1;\n");
        } else {
            asm volatile("cp.async.wait_group 0;\n");
        }
        __syncthreads();

        // yb partial dots: p = pixel (0..31), q = channel octant (0..7)
        {
            const int p = t & 31, q = t >> 5;
            float acc = 0.f;
            const float* tp_ = cur + (q * 32) * TP + p;
            const float* vp  = sv + q * 32;
#pragma unroll
            for (int c = 0; c < 32; c++) acc += vp[c] * tp_[c * TP];
            part[q * TP + p] = acc;
        }
        __syncthreads();
        if (t < TP) {
            float yb = b0;
#pragma unroll
            for (int q = 0; q < 8; q++) yb += part[q * TP + t];
            sy[t] = 1.f / (1.f + expf(-yb));
        }
        __syncthreads();

        // out = (g[c] + sigmoid(yb[p])) * x ; evict-first stores protect resident x
        const int base4 = tile * TP4;
#pragma unroll
        for (int j = 0; j < 8; j++) {
            int i4 = t + j * 256;
            int c = i4 >> 3, p4 = i4 & 7;
            float4 xv = cur4[i4];
            const float gv = sg[c];
            const int p = p4 * 4;
            float4 o;
            o.x = (gv + sy[p + 0]) * xv.x;
            o.y = (gv + sy[p + 1]) * xv.y;
            o.z = (gv + sy[p + 2]) * xv.z;
            o.w = (gv + sy[p + 3]) * xv.w;
            __stcs(&out4[(size_t)c * HW4 + base4 + p4], o);
        }
        __syncthreads();   // buffer-reuse safety before restaging `cur`
        tile = ntile;
        i++;
    }
}

// ---------------- Launch ----------------------------------------------------------
extern "C" void kernel_launch(void* const* d_in, const int* in_sizes, int n_in,
                              void* d_out, int out_size) {
    const float* x    = (const float*)d_in[0];
    const float* cv1w = (const float*)d_in[1];
    const float* cv1b = (const float*)d_in[2];
    // d_in[3], d_in[4] = ch_cv2_w/b : mathematically unused (softmax over size-1 dim)
    const float* cv3w = (const float*)d_in[5];
    const float* cv3b = (const float*)d_in[6];
    const float* lng  = (const float*)d_in[7];
    const float* lnb  = (const float*)d_in[8];
    const float* sp1w = (const float*)d_in[9];
    const float* sp1b = (const float*)d_in[10];
    const float* sp2w = (const float*)d_in[11];
    const float* sp2b = (const float*)d_in[12];

    int nsm = 148;
    cudaDeviceGetAttribute(&nsm, cudaDevAttrMultiProcessorCount, 0);
    const int grid3 = nsm * 3;   // 3 CTAs/SM at ~68KB smem each

    dim3 g1(SEGS, C);
    k1_sums<<<g1, 256>>>((const float4*)x);
    k2_scalars<<<1, 256>>>(cv1w, cv1b, cv3w, cv3b, lng, lnb, sp1w, sp1b, sp2w, sp2b);

    const int smem_bytes = (2 * TILE_F + C + C + 256 + TP) * (int)sizeof(float);
    cudaFuncSetAttribute(k3_out, cudaFuncAttributeMaxDynamicSharedMemorySize, smem_bytes);
    k3_out<<<grid3, 256, smem_bytes>>>((const float4*)x, (float4*)d_out, grid3);
}